// round 9
// baseline (speedup 1.0000x reference)
#include <cuda_runtime.h>
#include <cstdint>

// ---------------- problem constants ----------------
#define NB 4
#define NC 512
#define NG 2048
#define CH 3
#define OC 64
#define NBAS 10
#define NPT 8192
#define EPSV 1e-6f
#define BN_EPS 1e-5f

// output layout (float32, concatenated in return order)
#define OFF_Y   0
#define OFF_NF  524288
#define OFF_FP  598016
#define OFF_NH1 671744
#define OFF_H0  745472

// scratch (device globals)
__device__ float g_pos[9 * NPT];          // SoA [chan][b*NG+g]
__device__ float g_conv[9 * NPT];
__device__ float g_sx[NB * 3 * NC];       // sorted x per (b, coord)
__device__ float g_sy[NB * 3 * NC];       // y gathered by sort perm
__device__ unsigned long long g_isum[9];
__device__ unsigned long long g_isq[9];

#define S_SUM 1.7179869184e10   // 2^34
#define S_SQ  2.68435456e8      // 2^28

__device__ __forceinline__ float ex2f(float x) {
    float y;
    asm("ex2.approx.ftz.f32 %0, %1;" : "=f"(y) : "f"(x));
    return y;
}

// ============================================================
// Kernel 0: deterministic bitonic sort of x_c per (b, coord),
//           with y gathered by the permutation. 12 blocks x 512.
// ============================================================
__global__ void __launch_bounds__(NC)
k0_sort(const float* __restrict__ xc, const float* __restrict__ yc)
{
    __shared__ float sv[NC];
    __shared__ int   si[NC];
    const int bc = blockIdx.x;           // 0..11
    const int b = bc / 3, c = bc - b * 3;
    const int t = threadIdx.x;

    if (bc == 0 && t < 9) { g_isum[t] = 0ull; g_isq[t] = 0ull; }

    sv[t] = xc[(b * NC + t) * 3 + c];
    si[t] = t;
    __syncthreads();

    for (int k = 2; k <= NC; k <<= 1) {
        for (int j = k >> 1; j > 0; j >>= 1) {
            int ixj = t ^ j;
            if (ixj > t) {
                bool up = ((t & k) == 0);
                float a = sv[t], bb = sv[ixj];
                int ia = si[t], ib = si[ixj];
                bool sw = up ? (a > bb || (a == bb && ia > ib))
                             : (a < bb || (a == bb && ia < ib));
                if (sw) { sv[t] = bb; sv[ixj] = a; si[t] = ib; si[ixj] = ia; }
            }
            __syncthreads();
        }
    }
    g_sx[bc * NC + t] = sv[t];
    g_sy[bc * NC + t] = yc[(b * NC + si[t]) * 3 + c];
}

// ============================================================
// Kernel 1: sparse RBF sums + fourier prior.
//           Warp per (b,g); per coord, scan only the sorted
//           window |x_c - x_g| <= R = 8.5*(sigma_max+EPS).
// ============================================================
__global__ void __launch_bounds__(256)
k1_rbf(const float* __restrict__ xg, const float* __restrict__ sigma,
       const float* __restrict__ mu, const float* __restrict__ eps1,
       const float* __restrict__ bu, const float* __restrict__ rw,
       float* __restrict__ out)
{
    __shared__ float ssx[3 * NC];
    __shared__ float ssy[3 * NC];
    __shared__ float ssw[NBAS * 3];
    __shared__ float ssb[NBAS * 3];
    __shared__ float srw[NBAS];
    __shared__ float scoef[3];
    __shared__ float sR;

    const int b = blockIdx.y;
    const int tid = threadIdx.x;

    for (int idx = tid; idx < 3 * NC; idx += 256) {
        ssx[idx] = g_sx[b * 3 * NC + idx];
        ssy[idx] = g_sy[b * 3 * NC + idx];
    }
    if (tid < NBAS * 3) {
        int k = tid / 3, p = tid - k * 3;
        float w_std = 1.0f / (expf(sigma[p]) + EPSV);
        ssw[tid] = expf(mu[p]) + w_std * eps1[(b * NBAS + k) * 3 + p];
        ssb[tid] = 6.283185307179586f * bu[(b * NBAS + k) * 3 + p];
    }
    if (tid >= 32 && tid < 32 + NBAS) srw[tid - 32] = rw[tid - 32];
    if (tid >= 64 && tid < 67) {
        int p = tid - 64;
        float inv = 1.0f / (expf(sigma[p]) + EPSV);
        scoef[p] = -0.5f * inv * inv * 1.4426950408889634f;
    }
    if (tid == 96) {
        float s0 = expf(sigma[0]) + EPSV;
        float s1 = expf(sigma[1]) + EPSV;
        float s2 = expf(sigma[2]) + EPSV;
        sR = 8.5f * fmaxf(s0, fmaxf(s1, s2));
    }
    __syncthreads();

    const int wid = tid >> 5, lane = tid & 31;
    const int g = blockIdx.x * 8 + wid;
    const float* xgp = &xg[(b * NG + g) * 3];
    const float xg0 = xgp[0], xg1 = xgp[1], xg2 = xgp[2];
    const float c0 = scoef[0], c1 = scoef[1], c2 = scoef[2];
    const float R = sR;

    float h0[9], h1[9];

#pragma unroll
    for (int c = 0; c < 3; c++) {
        const float xgc = (c == 0) ? xg0 : ((c == 1) ? xg1 : xg2);
        const float* sx = ssx + c * NC;
        const float* sy = ssy + c * NC;
        const float tlo = xgc - R, thi = xgc + R;

        // branchless binary searches; step starts at NC=512 so the
        // bounds can reach 512 (R8 started at 256 -> cap 511, which
        // dropped the largest in-window context point: the R8 bug).
        int lo = 0, hi = 0;
#pragma unroll
        for (int st = 512; st > 0; st >>= 1) {
            int m = lo + st;
            if (m <= NC && sx[m - 1] < tlo) lo = m;
            int m2 = hi + st;
            if (m2 <= NC && sx[m2 - 1] <= thi) hi = m2;
        }

        float a0 = 0.f, a1 = 0.f, a2 = 0.f;
        float b0 = 0.f, b1 = 0.f, b2 = 0.f;
        for (int n = lo + lane; n < hi; n += 32) {
            float xv = sx[n];
            float yv = sy[n];
            float d = xv - xgc;
            float s = d * d;
            float e;
            e = ex2f(s * c0); a0 += e; b0 = fmaf(e, yv, b0);
            e = ex2f(s * c1); a1 += e; b1 = fmaf(e, yv, b1);
            e = ex2f(s * c2); a2 += e; b2 = fmaf(e, yv, b2);
        }
        h0[c * 3 + 0] = a0; h1[c * 3 + 0] = b0;
        h0[c * 3 + 1] = a1; h1[c * 3 + 1] = b1;
        h0[c * 3 + 2] = a2; h1[c * 3 + 2] = b2;
    }

    // warp butterfly reduction
#pragma unroll
    for (int off = 16; off > 0; off >>= 1) {
#pragma unroll
        for (int j = 0; j < 9; j++) {
            h0[j] += __shfl_xor_sync(0xffffffffu, h0[j], off);
            h1[j] += __shfl_xor_sync(0xffffffffu, h1[j], off);
        }
    }

    if (lane < 9) {
        float h0v = 0.f, h1v = 0.f;
        switch (lane) {
            case 0: h0v = h0[0]; h1v = h1[0]; break;
            case 1: h0v = h0[1]; h1v = h1[1]; break;
            case 2: h0v = h0[2]; h1v = h1[2]; break;
            case 3: h0v = h0[3]; h1v = h1[3]; break;
            case 4: h0v = h0[4]; h1v = h1[4]; break;
            case 5: h0v = h0[5]; h1v = h1[5]; break;
            case 6: h0v = h0[6]; h1v = h1[6]; break;
            case 7: h0v = h0[7]; h1v = h1[7]; break;
            case 8: h0v = h0[8]; h1v = h1[8]; break;
        }
        int c = lane / 3;
        int p = lane - c * 3;
        float xgc = (c == 0) ? xg0 : ((c == 1) ? xg1 : xg2);
        float nh1 = h1v / (h0v + EPSV);

        // mul-then-add (no FMA) to match reference fp32 arg exactly
        float fp = 0.f;
#pragma unroll
        for (int k = 0; k < NBAS; k++) {
            float arg = __fadd_rn(__fmul_rn(ssw[k * 3 + p], xgc), ssb[k * 3 + p]);
            fp += srw[k] * cosf(arg);
        }
        fp *= 0.4472135954999579f;

        int pt = b * NG + g;
        int base = pt * 9 + lane;
        out[OFF_H0 + base] = h0v;
        out[OFF_NH1 + base] = nh1;
        out[OFF_FP + base] = fp;
        g_pos[lane * NPT + pt] = nh1 + fp;
    }
}

// ============================================================
// Kernel 2: depthwise convs + deterministic BN partial sums.
//           144 blocks x 512; fp64 tree -> int64 fixed-point atomics.
// ============================================================
__global__ void __launch_bounds__(512)
k2_conv(const float* __restrict__ w1, const float* __restrict__ b1,
        const float* __restrict__ w2, const float* __restrict__ b2,
        const float* __restrict__ w3, const float* __restrict__ b3)
{
    __shared__ double ss[512], sq[512];
    const int tid = threadIdx.x;
    const int t = blockIdx.x * 512 + tid;
    const int chan = blockIdx.x >> 4;
    const int rem = t - chan * NPT;
    const int g = rem & (NG - 1);
    const int c = chan / 3, p = chan - c * 3;

    const int ksz = (p == 0) ? 3 : ((p == 1) ? 5 : 9);
    const int pad = ksz >> 1;
    const float* w  = (p == 0) ? w1 : ((p == 1) ? w2 : w3);
    const float* bb = (p == 0) ? b1 : ((p == 1) ? b2 : b3);

    float acc = bb[c];
    const float* src = &g_pos[t - g];
    for (int tt = 0; tt < ksz; tt++) {
        int gg = g + tt - pad;
        if (gg >= 0 && gg < NG)
            acc = fmaf(src[gg], w[c * ksz + tt], acc);
    }
    g_conv[t] = acc;

    double v = (double)acc;
    ss[tid] = v;
    sq[tid] = v * v;
    __syncthreads();
    for (int off = 256; off > 0; off >>= 1) {
        if (tid < off) { ss[tid] += ss[tid + off]; sq[tid] += sq[tid + off]; }
        __syncthreads();
    }
    if (tid == 0) {
        long long is = __double2ll_rn(ss[0] * S_SUM);
        long long iq = __double2ll_rn(sq[0] * S_SQ);
        atomicAdd(&g_isum[chan], (unsigned long long)is);
        atomicAdd(&g_isq[chan],  (unsigned long long)iq);
    }
}

// ============================================================
// Kernel 3: stats finalize + BN apply + n_f + linear head.
// ============================================================
__global__ void __launch_bounds__(256)
k3_head(const float* __restrict__ gamma, const float* __restrict__ beta,
        const float* __restrict__ gw, const float* __restrict__ gb,
        float* __restrict__ out)
{
    __shared__ float sfeat[32 * 19];
    __shared__ float swT[18 * 64];
    __shared__ float sbias[OC];
    __shared__ float sstat[18];
    __shared__ float sgam[9], sbet[9];

    const int tid = threadIdx.x;
    const int base = blockIdx.x * 32;

    for (int idx = tid; idx < OC * 18; idx += 256) {
        int o = idx / 18, k = idx - o * 18;
        swT[k * 64 + o] = gw[idx];
    }
    if (tid < OC) sbias[tid] = gb[tid];
    if (tid >= 96 && tid < 105) {
        int j = tid - 96;
        int c = j / 3, p = j - c * 3;
        sgam[j] = gamma[p * 3 + c];
        sbet[j] = beta[p * 3 + c];
    }
    if (tid >= 64 && tid < 73) {
        int j = tid - 64;
        double m  = (double)(long long)g_isum[j] * (1.0 / S_SUM) * (1.0 / 8192.0);
        double eq = (double)(long long)g_isq[j]  * (1.0 / S_SQ)  * (1.0 / 8192.0);
        double var = eq - m * m;
        if (var < 0.0) var = 0.0;
        sstat[j] = (float)m;
        sstat[9 + j] = (float)(1.0 / sqrt(var + (double)BN_EPS));
    }
    __syncthreads();

    for (int idx = tid; idx < 288; idx += 256)
        sfeat[(idx / 9) * 19 + (idx % 9)] = out[OFF_H0 + base * 9 + idx];
    for (int idx = tid; idx < 288; idx += 256) {
        int j = idx >> 5, t = idx & 31;
        float x = g_conv[j * NPT + base + t];
        sfeat[t * 19 + 9 + j] = sgam[j] * (x - sstat[j]) * sstat[9 + j] + sbet[j];
    }
    __syncthreads();

    for (int idx = tid; idx < 288; idx += 256)
        out[OFF_NF + base * 9 + idx] = sfeat[(idx / 9) * 19 + 9 + (idx % 9)];

    const int pt = tid >> 3;
    const int og = (tid & 7) * 8;
    const float* f = &sfeat[pt * 19];
    float acc[8];
#pragma unroll
    for (int oi = 0; oi < 8; oi++) acc[oi] = sbias[og + oi];
#pragma unroll
    for (int k = 0; k < 18; k++) {
        float fv = f[k];
        float4 wa = *reinterpret_cast<const float4*>(&swT[k * 64 + og]);
        float4 wb = *reinterpret_cast<const float4*>(&swT[k * 64 + og + 4]);
        acc[0] = fmaf(fv, wa.x, acc[0]);
        acc[1] = fmaf(fv, wa.y, acc[1]);
        acc[2] = fmaf(fv, wa.z, acc[2]);
        acc[3] = fmaf(fv, wa.w, acc[3]);
        acc[4] = fmaf(fv, wb.x, acc[4]);
        acc[5] = fmaf(fv, wb.y, acc[5]);
        acc[6] = fmaf(fv, wb.z, acc[6]);
        acc[7] = fmaf(fv, wb.w, acc[7]);
    }
    float* yo = &out[OFF_Y + (base + pt) * OC + og];
    *reinterpret_cast<float4*>(yo)     = make_float4(acc[0], acc[1], acc[2], acc[3]);
    *reinterpret_cast<float4*>(yo + 4) = make_float4(acc[4], acc[5], acc[6], acc[7]);
}

// ============================================================
extern "C" void kernel_launch(void* const* d_in, const int* in_sizes, int n_in,
                              void* d_out, int out_size)
{
    const float* xc    = (const float*)d_in[0];
    const float* yc    = (const float*)d_in[1];
    const float* xg    = (const float*)d_in[2];
    const float* sigma = (const float*)d_in[3];
    const float* mu    = (const float*)d_in[4];
    const float* eps1  = (const float*)d_in[5];
    const float* bu    = (const float*)d_in[6];
    const float* rw    = (const float*)d_in[7];
    const float* w1    = (const float*)d_in[8];
    const float* b1    = (const float*)d_in[9];
    const float* w2    = (const float*)d_in[10];
    const float* b2    = (const float*)d_in[11];
    const float* w3    = (const float*)d_in[12];
    const float* b3    = (const float*)d_in[13];
    const float* gamma = (const float*)d_in[14];
    const float* beta  = (const float*)d_in[15];
    const float* gw    = (const float*)d_in[16];
    const float* gb    = (const float*)d_in[17];
    float* out = (float*)d_out;

    k0_sort<<<NB * 3, NC>>>(xc, yc);
    dim3 grid1(NG / 8, NB);
    k1_rbf<<<grid1, 256>>>(xg, sigma, mu, eps1, bu, rw, out);
    k2_conv<<<144, 512>>>(w1, b1, w2, b2, w3, b3);
    k3_head<<<256, 256>>>(gamma, beta, gw, gb, out);
}

// round 10
// speedup vs baseline: 1.1369x; 1.1369x over previous
#include <cuda_runtime.h>
#include <cstdint>

// ---------------- problem constants ----------------
#define NB 4
#define NC 512
#define NG 2048
#define CH 3
#define OC 64
#define NBAS 10
#define NPT 8192
#define NBIN 64
#define EPSV 1e-6f
#define BN_EPS 1e-5f

// output layout (float32, concatenated in return order)
#define OFF_Y   0
#define OFF_NF  524288
#define OFF_FP  598016
#define OFF_NH1 671744
#define OFF_H0  745472

// scratch (device globals)
__device__ float g_pos[9 * NPT];          // SoA [chan][b*NG+g]
__device__ float g_conv[9 * NPT];
__device__ float2 g_sxy[NB * 3 * NC];     // bucketed (x,y) per (b,coord)
__device__ int   g_bstart[NB * 3 * (NBIN + 1)];
__device__ float g_binfo[NB * 3 * 2];     // min, scale per (b,coord)
__device__ unsigned long long g_isum[9];
__device__ unsigned long long g_isq[9];

#define S_SUM 1.7179869184e10   // 2^34
#define S_SQ  2.68435456e8      // 2^28

__device__ __forceinline__ float ex2f(float x) {
    float y;
    asm("ex2.approx.ftz.f32 %0, %1;" : "=f"(y) : "f"(x));
    return y;
}

// ============================================================
// Kernel 0: deterministic 64-bin bucket multisplit per (b,coord).
//           Stable (original-index order within bin) -> bitwise
//           deterministic. ~15 cheap syncs (vs 45 bitonic stages).
// ============================================================
__global__ void __launch_bounds__(NC)
k0_bucket(const float* __restrict__ xc, const float* __restrict__ yc)
{
    __shared__ float sx[NC], sy[NC];
    __shared__ int scnt[16 * NBIN];      // [warp][bin]
    __shared__ int stotal[NBIN];
    __shared__ int sbstart[NBIN + 1];
    __shared__ float wmn[16], wmx[16];
    __shared__ float sminv, sscale;

    const int bc = blockIdx.x;           // 0..11
    const int b = bc / 3, c = bc - b * 3;
    const int t = threadIdx.x;
    const int w = t >> 5, lane = t & 31;

    if (bc == 0 && t < 9) { g_isum[t] = 0ull; g_isq[t] = 0ull; }

    float x = xc[(b * NC + t) * 3 + c];
    float y = yc[(b * NC + t) * 3 + c];

    // zero per-warp histograms
    scnt[t] = 0;
    scnt[NC + t] = 0;

    // warp min/max
    float mn = x, mx = x;
#pragma unroll
    for (int off = 16; off > 0; off >>= 1) {
        mn = fminf(mn, __shfl_xor_sync(0xffffffffu, mn, off));
        mx = fmaxf(mx, __shfl_xor_sync(0xffffffffu, mx, off));
    }
    if (lane == 0) { wmn[w] = mn; wmx[w] = mx; }
    __syncthreads();
    if (t == 0) {
        float m = wmn[0], M = wmx[0];
#pragma unroll
        for (int i = 1; i < 16; i++) { m = fminf(m, wmn[i]); M = fmaxf(M, wmx[i]); }
        sminv = m;
        sscale = (M > m) ? 63.9999f / (M - m) : 0.0f;
    }
    __syncthreads();

    const float mnv = sminv, sc = sscale;
    int bin = (int)((x - mnv) * sc);
    bin = min(max(bin, 0), NBIN - 1);

    unsigned msk = __match_any_sync(0xffffffffu, bin);
    int rank = __popc(msk & ((1u << lane) - 1u));
    if (rank == 0) scnt[w * NBIN + bin] = __popc(msk);
    __syncthreads();

    // per-bin scan across warps (threads 0..63)
    if (t < NBIN) {
        int run = 0;
#pragma unroll
        for (int w2 = 0; w2 < 16; w2++) {
            int v = scnt[w2 * NBIN + t];
            scnt[w2 * NBIN + t] = run;
            run += v;
        }
        stotal[t] = run;
    }
    __syncthreads();

    // exclusive scan over 64 bins (Hillis-Steele)
    for (int off = 1; off < NBIN; off <<= 1) {
        int v = 0;
        if (t < NBIN && t >= off) v = stotal[t - off];
        __syncthreads();
        if (t < NBIN && t >= off) stotal[t] += v;
        __syncthreads();
    }
    if (t < NBIN) sbstart[t + 1] = stotal[t];
    if (t == 0) sbstart[0] = 0;
    __syncthreads();

    int pos = sbstart[bin] + scnt[w * NBIN + bin] + rank;
    sx[pos] = x;
    sy[pos] = y;
    __syncthreads();

    g_sxy[bc * NC + t] = make_float2(sx[t], sy[t]);
    if (t < NBIN + 1) g_bstart[bc * (NBIN + 1) + t] = sbstart[t];
    if (t == 0) { g_binfo[bc * 2] = mnv; g_binfo[bc * 2 + 1] = sc; }
}

// ============================================================
// Kernel 1: windowed RBF sums + fourier prior. Warp per (b,g).
//           Per (coord,param): window |x_c-x_g| <= 8.5*(sig_p+eps)
//           via bucket-boundary lookup (superset of exact window).
// ============================================================
__global__ void __launch_bounds__(256)
k1_rbf(const float* __restrict__ xg, const float* __restrict__ sigma,
       const float* __restrict__ mu, const float* __restrict__ eps1,
       const float* __restrict__ bu, const float* __restrict__ rw,
       float* __restrict__ out)
{
    __shared__ float2 sxy[3 * NC];
    __shared__ int sbs[3 * (NBIN + 1)];
    __shared__ float sminf[3], sscalef[3];
    __shared__ float ssw[NBAS * 3], ssb[NBAS * 3], srw[NBAS];
    __shared__ float scoef[3], sRR[3];

    const int b = blockIdx.y;
    const int tid = threadIdx.x;

    for (int idx = tid; idx < 3 * NC; idx += 256)
        sxy[idx] = g_sxy[b * 3 * NC + idx];
    for (int idx = tid; idx < 3 * (NBIN + 1); idx += 256)
        sbs[idx] = g_bstart[b * 3 * (NBIN + 1) + idx];
    if (tid < 3) {
        sminf[tid]   = g_binfo[(b * 3 + tid) * 2];
        sscalef[tid] = g_binfo[(b * 3 + tid) * 2 + 1];
    }
    if (tid >= 128 && tid < 128 + NBAS * 3) {
        int q = tid - 128;
        int k = q / 3, p = q - k * 3;
        float w_std = 1.0f / (expf(sigma[p]) + EPSV);
        ssw[q] = expf(mu[p]) + w_std * eps1[(b * NBAS + k) * 3 + p];
        ssb[q] = 6.283185307179586f * bu[(b * NBAS + k) * 3 + p];
    }
    if (tid >= 160 && tid < 160 + NBAS) srw[tid - 160] = rw[tid - 160];
    if (tid >= 176 && tid < 179) {
        int p = tid - 176;
        float s = expf(sigma[p]) + EPSV;
        float inv = 1.0f / s;
        scoef[p] = -0.5f * inv * inv * 1.4426950408889634f;
        sRR[p] = 8.5f * s;
    }
    __syncthreads();

    const int wid = tid >> 5, lane = tid & 31;
    const int g = blockIdx.x * 8 + wid;
    const float* xgp = &xg[(b * NG + g) * 3];
    const float xgv[3] = { xgp[0], xgp[1], xgp[2] };

    float h0[9], h1[9];

#pragma unroll
    for (int c = 0; c < 3; c++) {
        const float xgc = xgv[c];
        const float2* sp = sxy + c * NC;
        const int* bsc = sbs + c * (NBIN + 1);
        const float mnc = sminf[c], scc = sscalef[c];
#pragma unroll
        for (int p = 0; p < 3; p++) {
            const float R = sRR[p];
            const float cp = scoef[p];
            int il = (int)floorf((xgc - R - mnc) * scc);
            int ih = (int)floorf((xgc + R - mnc) * scc);
            il = min(max(il, 0), NBIN - 1);
            ih = min(max(ih, 0), NBIN - 1);
            const int lo = bsc[il], hi = bsc[ih + 1];

            float a = 0.f, bb = 0.f;
            for (int n = lo + lane; n < hi; n += 32) {
                float2 v = sp[n];
                float d = v.x - xgc;
                float e = ex2f(d * d * cp);
                a += e;
                bb = fmaf(e, v.y, bb);
            }
            h0[c * 3 + p] = a;
            h1[c * 3 + p] = bb;
        }
    }

    // warp butterfly reduction
#pragma unroll
    for (int off = 16; off > 0; off >>= 1) {
#pragma unroll
        for (int j = 0; j < 9; j++) {
            h0[j] += __shfl_xor_sync(0xffffffffu, h0[j], off);
            h1[j] += __shfl_xor_sync(0xffffffffu, h1[j], off);
        }
    }

    if (lane < 9) {
        float h0v = 0.f, h1v = 0.f;
        switch (lane) {
            case 0: h0v = h0[0]; h1v = h1[0]; break;
            case 1: h0v = h0[1]; h1v = h1[1]; break;
            case 2: h0v = h0[2]; h1v = h1[2]; break;
            case 3: h0v = h0[3]; h1v = h1[3]; break;
            case 4: h0v = h0[4]; h1v = h1[4]; break;
            case 5: h0v = h0[5]; h1v = h1[5]; break;
            case 6: h0v = h0[6]; h1v = h1[6]; break;
            case 7: h0v = h0[7]; h1v = h1[7]; break;
            case 8: h0v = h0[8]; h1v = h1[8]; break;
        }
        int c = lane / 3;
        int p = lane - c * 3;
        float xgc = xgv[c];
        float nh1 = h1v / (h0v + EPSV);

        // mul-then-add (no FMA) to match reference fp32 arg exactly
        float fp = 0.f;
#pragma unroll
        for (int k = 0; k < NBAS; k++) {
            float arg = __fadd_rn(__fmul_rn(ssw[k * 3 + p], xgc), ssb[k * 3 + p]);
            fp += srw[k] * cosf(arg);
        }
        fp *= 0.4472135954999579f;

        int pt = b * NG + g;
        int base = pt * 9 + lane;
        out[OFF_H0 + base] = h0v;
        out[OFF_NH1 + base] = nh1;
        out[OFF_FP + base] = fp;
        g_pos[lane * NPT + pt] = nh1 + fp;
    }
}

// ============================================================
// Kernel 2: depthwise convs + deterministic BN partial sums.
// ============================================================
__global__ void __launch_bounds__(512)
k2_conv(const float* __restrict__ w1, const float* __restrict__ b1,
        const float* __restrict__ w2, const float* __restrict__ b2,
        const float* __restrict__ w3, const float* __restrict__ b3)
{
    __shared__ double ss[512], sq[512];
    const int tid = threadIdx.x;
    const int t = blockIdx.x * 512 + tid;
    const int chan = blockIdx.x >> 4;
    const int rem = t - chan * NPT;
    const int g = rem & (NG - 1);
    const int c = chan / 3, p = chan - c * 3;

    const int ksz = (p == 0) ? 3 : ((p == 1) ? 5 : 9);
    const int pad = ksz >> 1;
    const float* w  = (p == 0) ? w1 : ((p == 1) ? w2 : w3);
    const float* bb = (p == 0) ? b1 : ((p == 1) ? b2 : b3);

    float acc = bb[c];
    const float* src = &g_pos[t - g];
    for (int tt = 0; tt < ksz; tt++) {
        int gg = g + tt - pad;
        if (gg >= 0 && gg < NG)
            acc = fmaf(src[gg], w[c * ksz + tt], acc);
    }
    g_conv[t] = acc;

    double v = (double)acc;
    ss[tid] = v;
    sq[tid] = v * v;
    __syncthreads();
    for (int off = 256; off > 0; off >>= 1) {
        if (tid < off) { ss[tid] += ss[tid + off]; sq[tid] += sq[tid + off]; }
        __syncthreads();
    }
    if (tid == 0) {
        long long is = __double2ll_rn(ss[0] * S_SUM);
        long long iq = __double2ll_rn(sq[0] * S_SQ);
        atomicAdd(&g_isum[chan], (unsigned long long)is);
        atomicAdd(&g_isq[chan],  (unsigned long long)iq);
    }
}

// ============================================================
// Kernel 3: stats finalize + BN apply + n_f + linear head.
// ============================================================
__global__ void __launch_bounds__(256)
k3_head(const float* __restrict__ gamma, const float* __restrict__ beta,
        const float* __restrict__ gw, const float* __restrict__ gb,
        float* __restrict__ out)
{
    __shared__ float sfeat[32 * 19];
    __shared__ float swT[18 * 64];
    __shared__ float sbias[OC];
    __shared__ float sstat[18];
    __shared__ float sgam[9], sbet[9];

    const int tid = threadIdx.x;
    const int base = blockIdx.x * 32;

    for (int idx = tid; idx < OC * 18; idx += 256) {
        int o = idx / 18, k = idx - o * 18;
        swT[k * 64 + o] = gw[idx];
    }
    if (tid < OC) sbias[tid] = gb[tid];
    if (tid >= 96 && tid < 105) {
        int j = tid - 96;
        int c = j / 3, p = j - c * 3;
        sgam[j] = gamma[p * 3 + c];
        sbet[j] = beta[p * 3 + c];
    }
    if (tid >= 64 && tid < 73) {
        int j = tid - 64;
        double m  = (double)(long long)g_isum[j] * (1.0 / S_SUM) * (1.0 / 8192.0);
        double eq = (double)(long long)g_isq[j]  * (1.0 / S_SQ)  * (1.0 / 8192.0);
        double var = eq - m * m;
        if (var < 0.0) var = 0.0;
        sstat[j] = (float)m;
        sstat[9 + j] = (float)(1.0 / sqrt(var + (double)BN_EPS));
    }
    __syncthreads();

    for (int idx = tid; idx < 288; idx += 256)
        sfeat[(idx / 9) * 19 + (idx % 9)] = out[OFF_H0 + base * 9 + idx];
    for (int idx = tid; idx < 288; idx += 256) {
        int j = idx >> 5, t = idx & 31;
        float x = g_conv[j * NPT + base + t];
        sfeat[t * 19 + 9 + j] = sgam[j] * (x - sstat[j]) * sstat[9 + j] + sbet[j];
    }
    __syncthreads();

    for (int idx = tid; idx < 288; idx += 256)
        out[OFF_NF + base * 9 + idx] = sfeat[(idx / 9) * 19 + 9 + (idx % 9)];

    const int pt = tid >> 3;
    const int og = (tid & 7) * 8;
    const float* f = &sfeat[pt * 19];
    float acc[8];
#pragma unroll
    for (int oi = 0; oi < 8; oi++) acc[oi] = sbias[og + oi];
#pragma unroll
    for (int k = 0; k < 18; k++) {
        float fv = f[k];
        float4 wa = *reinterpret_cast<const float4*>(&swT[k * 64 + og]);
        float4 wb = *reinterpret_cast<const float4*>(&swT[k * 64 + og + 4]);
        acc[0] = fmaf(fv, wa.x, acc[0]);
        acc[1] = fmaf(fv, wa.y, acc[1]);
        acc[2] = fmaf(fv, wa.z, acc[2]);
        acc[3] = fmaf(fv, wa.w, acc[3]);
        acc[4] = fmaf(fv, wb.x, acc[4]);
        acc[5] = fmaf(fv, wb.y, acc[5]);
        acc[6] = fmaf(fv, wb.z, acc[6]);
        acc[7] = fmaf(fv, wb.w, acc[7]);
    }
    float* yo = &out[OFF_Y + (base + pt) * OC + og];
    *reinterpret_cast<float4*>(yo)     = make_float4(acc[0], acc[1], acc[2], acc[3]);
    *reinterpret_cast<float4*>(yo + 4) = make_float4(acc[4], acc[5], acc[6], acc[7]);
}

// ============================================================
extern "C" void kernel_launch(void* const* d_in, const int* in_sizes, int n_in,
                              void* d_out, int out_size)
{
    const float* xc    = (const float*)d_in[0];
    const float* yc    = (const float*)d_in[1];
    const float* xg    = (const float*)d_in[2];
    const float* sigma = (const float*)d_in[3];
    const float* mu    = (const float*)d_in[4];
    const float* eps1  = (const float*)d_in[5];
    const float* bu    = (const float*)d_in[6];
    const float* rw    = (const float*)d_in[7];
    const float* w1    = (const float*)d_in[8];
    const float* b1    = (const float*)d_in[9];
    const float* w2    = (const float*)d_in[10];
    const float* b2    = (const float*)d_in[11];
    const float* w3    = (const float*)d_in[12];
    const float* b3    = (const float*)d_in[13];
    const float* gamma = (const float*)d_in[14];
    const float* beta  = (const float*)d_in[15];
    const float* gw    = (const float*)d_in[16];
    const float* gb    = (const float*)d_in[17];
    float* out = (float*)d_out;

    k0_bucket<<<NB * 3, NC>>>(xc, yc);
    dim3 grid1(NG / 8, NB);
    k1_rbf<<<grid1, 256>>>(xg, sigma, mu, eps1, bu, rw, out);
    k2_conv<<<144, 512>>>(w1, b1, w2, b2, w3, b3);
    k3_head<<<256, 256>>>(gamma, beta, gw, gb, out);
}

// round 12
// speedup vs baseline: 1.3117x; 1.1538x over previous
#include <cuda_runtime.h>
#include <cstdint>

// ---------------- problem constants ----------------
#define NB 4
#define NC 512
#define NG 2048
#define CH 3
#define OC 64
#define NBAS 10
#define NPT 8192
#define NBIN 64
#define EPSV 1e-6f
#define BN_EPS 1e-5f

// output layout (float32, concatenated in return order)
#define OFF_Y   0
#define OFF_NF  524288
#define OFF_FP  598016
#define OFF_NH1 671744
#define OFF_H0  745472

// scratch (device globals)
__device__ float g_pos[9 * NPT];          // SoA [chan][b*NG+g]
__device__ float g_conv[9 * NPT];
__device__ float2 g_sxy[NB * 3 * NC];     // bucketed (x,y) per (b,coord)
__device__ int   g_bstart[NB * 3 * (NBIN + 1)];
__device__ float g_binfo[NB * 3 * 2];     // min, scale per (b,coord)
__device__ unsigned long long g_isum[9];
__device__ unsigned long long g_isq[9];

#define S_SUM 1.7179869184e10   // 2^34
#define S_SQ  2.68435456e8      // 2^28

__device__ __forceinline__ float ex2f(float x) {
    float y;
    asm("ex2.approx.ftz.f32 %0, %1;" : "=f"(y) : "f"(x));
    return y;
}

// ============================================================
// Kernel 0: deterministic 64-bin bucket multisplit per (b,coord).
//           Stable (original-index order within bin) -> bitwise
//           deterministic. Proven in R10.
// ============================================================
__global__ void __launch_bounds__(NC)
k0_bucket(const float* __restrict__ xc, const float* __restrict__ yc)
{
    __shared__ float sx[NC], sy[NC];
    __shared__ int scnt[16 * NBIN];      // [warp][bin]
    __shared__ int stotal[NBIN];
    __shared__ int sbstart[NBIN + 1];
    __shared__ float wmn[16], wmx[16];
    __shared__ float sminv, sscale;

    const int bc = blockIdx.x;           // 0..11
    const int b = bc / 3, c = bc - b * 3;
    const int t = threadIdx.x;
    const int w = t >> 5, lane = t & 31;

    if (bc == 0 && t < 9) { g_isum[t] = 0ull; g_isq[t] = 0ull; }

    float x = xc[(b * NC + t) * 3 + c];
    float y = yc[(b * NC + t) * 3 + c];

    // zero per-warp histograms
    scnt[t] = 0;
    scnt[NC + t] = 0;

    // warp min/max
    float mn = x, mx = x;
#pragma unroll
    for (int off = 16; off > 0; off >>= 1) {
        mn = fminf(mn, __shfl_xor_sync(0xffffffffu, mn, off));
        mx = fmaxf(mx, __shfl_xor_sync(0xffffffffu, mx, off));
    }
    if (lane == 0) { wmn[w] = mn; wmx[w] = mx; }
    __syncthreads();
    if (t == 0) {
        float m = wmn[0], M = wmx[0];
#pragma unroll
        for (int i = 1; i < 16; i++) { m = fminf(m, wmn[i]); M = fmaxf(M, wmx[i]); }
        sminv = m;
        sscale = (M > m) ? 63.9999f / (M - m) : 0.0f;
    }
    __syncthreads();

    const float mnv = sminv, sc = sscale;
    int bin = (int)((x - mnv) * sc);
    bin = min(max(bin, 0), NBIN - 1);

    unsigned msk = __match_any_sync(0xffffffffu, bin);
    int rank = __popc(msk & ((1u << lane) - 1u));
    if (rank == 0) scnt[w * NBIN + bin] = __popc(msk);
    __syncthreads();

    // per-bin scan across warps (threads 0..63)
    if (t < NBIN) {
        int run = 0;
#pragma unroll
        for (int w2 = 0; w2 < 16; w2++) {
            int v = scnt[w2 * NBIN + t];
            scnt[w2 * NBIN + t] = run;
            run += v;
        }
        stotal[t] = run;
    }
    __syncthreads();

    // exclusive scan over 64 bins (Hillis-Steele)
    for (int off = 1; off < NBIN; off <<= 1) {
        int v = 0;
        if (t < NBIN && t >= off) v = stotal[t - off];
        __syncthreads();
        if (t < NBIN && t >= off) stotal[t] += v;
        __syncthreads();
    }
    if (t < NBIN) sbstart[t + 1] = stotal[t];
    if (t == 0) sbstart[0] = 0;
    __syncthreads();

    int pos = sbstart[bin] + scnt[w * NBIN + bin] + rank;
    sx[pos] = x;
    sy[pos] = y;
    __syncthreads();

    g_sxy[bc * NC + t] = make_float2(sx[t], sy[t]);
    if (t < NBIN + 1) g_bstart[bc * (NBIN + 1) + t] = sbstart[t];
    if (t == 0) { g_binfo[bc * 2] = mnv; g_binfo[bc * 2 + 1] = sc; }
}

// ============================================================
// Kernel 1: windowed RBF sums + fourier prior. Warp per (b,g).
//           Per coord: ONE union window R = 8.5*(sigma_max+eps),
//           3 exps per visit (good amortization: 18 issue / 3 MUFU).
// ============================================================
__global__ void __launch_bounds__(256)
k1_rbf(const float* __restrict__ xg, const float* __restrict__ sigma,
       const float* __restrict__ mu, const float* __restrict__ eps1,
       const float* __restrict__ bu, const float* __restrict__ rw,
       float* __restrict__ out)
{
    __shared__ float2 sxy[3 * NC];
    __shared__ int sbs[3 * (NBIN + 1)];
    __shared__ float sminf[3], sscalef[3];
    __shared__ float ssw[NBAS * 3], ssb[NBAS * 3], srw[NBAS];
    __shared__ float scoef[3];
    __shared__ float sRmax;

    const int b = blockIdx.y;
    const int tid = threadIdx.x;

    for (int idx = tid; idx < 3 * NC; idx += 256)
        sxy[idx] = g_sxy[b * 3 * NC + idx];
    for (int idx = tid; idx < 3 * (NBIN + 1); idx += 256)
        sbs[idx] = g_bstart[b * 3 * (NBIN + 1) + idx];
    if (tid < 3) {
        sminf[tid]   = g_binfo[(b * 3 + tid) * 2];
        sscalef[tid] = g_binfo[(b * 3 + tid) * 2 + 1];
    }
    if (tid >= 128 && tid < 128 + NBAS * 3) {
        int q = tid - 128;
        int k = q / 3, p = q - k * 3;
        float w_std = 1.0f / (expf(sigma[p]) + EPSV);
        ssw[q] = expf(mu[p]) + w_std * eps1[(b * NBAS + k) * 3 + p];
        ssb[q] = 6.283185307179586f * bu[(b * NBAS + k) * 3 + p];
    }
    if (tid >= 160 && tid < 160 + NBAS) srw[tid - 160] = rw[tid - 160];
    if (tid >= 176 && tid < 179) {
        int p = tid - 176;
        float s = expf(sigma[p]) + EPSV;
        float inv = 1.0f / s;
        scoef[p] = -0.5f * inv * inv * 1.4426950408889634f;
    }
    if (tid == 192) {
        float s0 = expf(sigma[0]) + EPSV;
        float s1 = expf(sigma[1]) + EPSV;
        float s2 = expf(sigma[2]) + EPSV;
        sRmax = 8.5f * fmaxf(s0, fmaxf(s1, s2));
    }
    __syncthreads();

    const int wid = tid >> 5, lane = tid & 31;
    const int g = blockIdx.x * 8 + wid;
    const float* xgp = &xg[(b * NG + g) * 3];
    const float xgv[3] = { xgp[0], xgp[1], xgp[2] };
    const float c0 = scoef[0], c1 = scoef[1], c2 = scoef[2];
    const float R = sRmax;

    float h0[9], h1[9];

#pragma unroll
    for (int c = 0; c < 3; c++) {
        const float xgc = xgv[c];
        const float2* sp = sxy + c * NC;
        const int* bsc = sbs + c * (NBIN + 1);
        const float mnc = sminf[c], scc = sscalef[c];

        int il = (int)floorf((xgc - R - mnc) * scc);
        int ih = (int)floorf((xgc + R - mnc) * scc);
        il = min(max(il, 0), NBIN - 1);
        ih = min(max(ih, 0), NBIN - 1);
        const int lo = bsc[il], hi = bsc[ih + 1];

        float a0 = 0.f, a1 = 0.f, a2 = 0.f;
        float b0 = 0.f, b1 = 0.f, b2 = 0.f;
        for (int n = lo + lane; n < hi; n += 32) {
            float2 v = sp[n];
            float d = v.x - xgc;
            float s = d * d;
            float e;
            e = ex2f(s * c0); a0 += e; b0 = fmaf(e, v.y, b0);
            e = ex2f(s * c1); a1 += e; b1 = fmaf(e, v.y, b1);
            e = ex2f(s * c2); a2 += e; b2 = fmaf(e, v.y, b2);
        }
        h0[c * 3 + 0] = a0; h1[c * 3 + 0] = b0;
        h0[c * 3 + 1] = a1; h1[c * 3 + 1] = b1;
        h0[c * 3 + 2] = a2; h1[c * 3 + 2] = b2;
    }

    // warp butterfly reduction
#pragma unroll
    for (int off = 16; off > 0; off >>= 1) {
#pragma unroll
        for (int j = 0; j < 9; j++) {
            h0[j] += __shfl_xor_sync(0xffffffffu, h0[j], off);
            h1[j] += __shfl_xor_sync(0xffffffffu, h1[j], off);
        }
    }

    if (lane < 9) {
        float h0v = 0.f, h1v = 0.f;
        switch (lane) {
            case 0: h0v = h0[0]; h1v = h1[0]; break;
            case 1: h0v = h0[1]; h1v = h1[1]; break;
            case 2: h0v = h0[2]; h1v = h1[2]; break;
            case 3: h0v = h0[3]; h1v = h1[3]; break;
            case 4: h0v = h0[4]; h1v = h1[4]; break;
            case 5: h0v = h0[5]; h1v = h1[5]; break;
            case 6: h0v = h0[6]; h1v = h1[6]; break;
            case 7: h0v = h0[7]; h1v = h1[7]; break;
            case 8: h0v = h0[8]; h1v = h1[8]; break;
        }
        int c = lane / 3;
        int p = lane - c * 3;
        float xgc = xgv[c];
        float nh1 = h1v / (h0v + EPSV);

        // mul-then-add (no FMA) to match reference fp32 arg exactly
        float fp = 0.f;
#pragma unroll
        for (int k = 0; k < NBAS; k++) {
            float arg = __fadd_rn(__fmul_rn(ssw[k * 3 + p], xgc), ssb[k * 3 + p]);
            fp += srw[k] * cosf(arg);
        }
        fp *= 0.4472135954999579f;

        int pt = b * NG + g;
        int base = pt * 9 + lane;
        out[OFF_H0 + base] = h0v;
        out[OFF_NH1 + base] = nh1;
        out[OFF_FP + base] = fp;
        g_pos[lane * NPT + pt] = nh1 + fp;
    }
}

// ============================================================
// Kernel 2: depthwise convs + deterministic BN partial sums.
// ============================================================
__global__ void __launch_bounds__(512)
k2_conv(const float* __restrict__ w1, const float* __restrict__ b1,
        const float* __restrict__ w2, const float* __restrict__ b2,
        const float* __restrict__ w3, const float* __restrict__ b3)
{
    __shared__ double ss[512], sq[512];
    const int tid = threadIdx.x;
    const int t = blockIdx.x * 512 + tid;
    const int chan = blockIdx.x >> 4;
    const int rem = t - chan * NPT;
    const int g = rem & (NG - 1);
    const int c = chan / 3, p = chan - c * 3;

    const int ksz = (p == 0) ? 3 : ((p == 1) ? 5 : 9);
    const int pad = ksz >> 1;
    const float* w  = (p == 0) ? w1 : ((p == 1) ? w2 : w3);
    const float* bb = (p == 0) ? b1 : ((p == 1) ? b2 : b3);

    float acc = bb[c];
    const float* src = &g_pos[t - g];
    for (int tt = 0; tt < ksz; tt++) {
        int gg = g + tt - pad;
        if (gg >= 0 && gg < NG)
            acc = fmaf(src[gg], w[c * ksz + tt], acc);
    }
    g_conv[t] = acc;

    double v = (double)acc;
    ss[tid] = v;
    sq[tid] = v * v;
    __syncthreads();
    for (int off = 256; off > 0; off >>= 1) {
        if (tid < off) { ss[tid] += ss[tid + off]; sq[tid] += sq[tid + off]; }
        __syncthreads();
    }
    if (tid == 0) {
        long long is = __double2ll_rn(ss[0] * S_SUM);
        long long iq = __double2ll_rn(sq[0] * S_SQ);
        atomicAdd(&g_isum[chan], (unsigned long long)is);
        atomicAdd(&g_isq[chan],  (unsigned long long)iq);
    }
}

// ============================================================
// Kernel 3: stats finalize + BN apply + n_f + linear head.
// ============================================================
__global__ void __launch_bounds__(256)
k3_head(const float* __restrict__ gamma, const float* __restrict__ beta,
        const float* __restrict__ gw, const float* __restrict__ gb,
        float* __restrict__ out)
{
    __shared__ float sfeat[32 * 19];
    __shared__ float swT[18 * 64];
    __shared__ float sbias[OC];
    __shared__ float sstat[18];
    __shared__ float sgam[9], sbet[9];

    const int tid = threadIdx.x;
    const int base = blockIdx.x * 32;

    for (int idx = tid; idx < OC * 18; idx += 256) {
        int o = idx / 18, k = idx - o * 18;
        swT[k * 64 + o] = gw[idx];
    }
    if (tid < OC) sbias[tid] = gb[tid];
    if (tid >= 96 && tid < 105) {
        int j = tid - 96;
        int c = j / 3, p = j - c * 3;
        sgam[j] = gamma[p * 3 + c];
        sbet[j] = beta[p * 3 + c];
    }
    if (tid >= 64 && tid < 73) {
        int j = tid - 64;
        double m  = (double)(long long)g_isum[j] * (1.0 / S_SUM) * (1.0 / 8192.0);
        double eq = (double)(long long)g_isq[j]  * (1.0 / S_SQ)  * (1.0 / 8192.0);
        double var = eq - m * m;
        if (var < 0.0) var = 0.0;
        sstat[j] = (float)m;
        sstat[9 + j] = (float)(1.0 / sqrt(var + (double)BN_EPS));
    }
    __syncthreads();

    for (int idx = tid; idx < 288; idx += 256)
        sfeat[(idx / 9) * 19 + (idx % 9)] = out[OFF_H0 + base * 9 + idx];
    for (int idx = tid; idx < 288; idx += 256) {
        int j = idx >> 5, t = idx & 31;
        float x = g_conv[j * NPT + base + t];
        sfeat[t * 19 + 9 + j] = sgam[j] * (x - sstat[j]) * sstat[9 + j] + sbet[j];
    }
    __syncthreads();

    for (int idx = tid; idx < 288; idx += 256)
        out[OFF_NF + base * 9 + idx] = sfeat[(idx / 9) * 19 + 9 + (idx % 9)];

    const int pt = tid >> 3;
    const int og = (tid & 7) * 8;
    const float* f = &sfeat[pt * 19];
    float acc[8];
#pragma unroll
    for (int oi = 0; oi < 8; oi++) acc[oi] = sbias[og + oi];
#pragma unroll
    for (int k = 0; k < 18; k++) {
        float fv = f[k];
        float4 wa = *reinterpret_cast<const float4*>(&swT[k * 64 + og]);
        float4 wb = *reinterpret_cast<const float4*>(&swT[k * 64 + og + 4]);
        acc[0] = fmaf(fv, wa.x, acc[0]);
        acc[1] = fmaf(fv, wa.y, acc[1]);
        acc[2] = fmaf(fv, wa.z, acc[2]);
        acc[3] = fmaf(fv, wa.w, acc[3]);
        acc[4] = fmaf(fv, wb.x, acc[4]);
        acc[5] = fmaf(fv, wb.y, acc[5]);
        acc[6] = fmaf(fv, wb.z, acc[6]);
        acc[7] = fmaf(fv, wb.w, acc[7]);
    }
    float* yo = &out[OFF_Y + (base + pt) * OC + og];
    *reinterpret_cast<float4*>(yo)     = make_float4(acc[0], acc[1], acc[2], acc[3]);
    *reinterpret_cast<float4*>(yo + 4) = make_float4(acc[4], acc[5], acc[6], acc[7]);
}

// ============================================================
extern "C" void kernel_launch(void* const* d_in, const int* in_sizes, int n_in,
                              void* d_out, int out_size)
{
    const float* xc    = (const float*)d_in[0];
    const float* yc    = (const float*)d_in[1];
    const float* xg    = (const float*)d_in[2];
    const float* sigma = (const float*)d_in[3];
    const float* mu    = (const float*)d_in[4];
    const float* eps1  = (const float*)d_in[5];
    const float* bu    = (const float*)d_in[6];
    const float* rw    = (const float*)d_in[7];
    const float* w1    = (const float*)d_in[8];
    const float* b1    = (const float*)d_in[9];
    const float* w2    = (const float*)d_in[10];
    const float* b2    = (const float*)d_in[11];
    const float* w3    = (const float*)d_in[12];
    const float* b3    = (const float*)d_in[13];
    const float* gamma = (const float*)d_in[14];
    const float* beta  = (const float*)d_in[15];
    const float* gw    = (const float*)d_in[16];
    const float* gb    = (const float*)d_in[17];
    float* out = (float*)d_out;

    k0_bucket<<<NB * 3, NC>>>(xc, yc);
    dim3 grid1(NG / 8, NB);
    k1_rbf<<<grid1, 256>>>(xg, sigma, mu, eps1, bu, rw, out);
    k2_conv<<<144, 512>>>(w1, b1, w2, b2, w3, b3);
    k3_head<<<256, 256>>>(gamma, beta, gw, gb, out);
}

// round 13
// speedup vs baseline: 1.3130x; 1.0010x over previous
#include <cuda_runtime.h>
#include <cstdint>

// ---------------- problem constants ----------------
#define NB 4
#define NC 512
#define NG 2048
#define CH 3
#define OC 64
#define NBAS 10
#define NPT 8192
#define NBIN 64
#define EPSV 1e-6f
#define BN_EPS 1e-5f

// output layout (float32, concatenated in return order)
#define OFF_Y   0
#define OFF_NF  524288
#define OFF_FP  598016
#define OFF_NH1 671744
#define OFF_H0  745472

// scratch (device globals)
__device__ float g_pos[9 * NPT];          // SoA [chan][b*NG+g]
__device__ float g_conv[9 * NPT];
__device__ float2 g_sxy[NB * 3 * NC];     // bucketed (x,y) per (b,coord)
__device__ int   g_bstart[NB * 3 * (NBIN + 1)];
__device__ float g_binfo[NB * 3 * 2];     // min, scale per (b,coord)
__device__ unsigned long long g_isum[9];
__device__ unsigned long long g_isq[9];

#define S_SUM 1.7179869184e10   // 2^34
#define S_SQ  2.68435456e8      // 2^28

__device__ __forceinline__ float ex2f(float x) {
    float y;
    asm("ex2.approx.ftz.f32 %0, %1;" : "=f"(y) : "f"(x));
    return y;
}

// ============================================================
// Kernel 0: deterministic 64-bin bucket multisplit per (b,coord).
//           (unchanged from R12 -- proven)
// ============================================================
__global__ void __launch_bounds__(NC)
k0_bucket(const float* __restrict__ xc, const float* __restrict__ yc)
{
    __shared__ float sx[NC], sy[NC];
    __shared__ int scnt[16 * NBIN];      // [warp][bin]
    __shared__ int stotal[NBIN];
    __shared__ int sbstart[NBIN + 1];
    __shared__ float wmn[16], wmx[16];
    __shared__ float sminv, sscale;

    const int bc = blockIdx.x;           // 0..11
    const int b = bc / 3, c = bc - b * 3;
    const int t = threadIdx.x;
    const int w = t >> 5, lane = t & 31;

    if (bc == 0 && t < 9) { g_isum[t] = 0ull; g_isq[t] = 0ull; }

    float x = xc[(b * NC + t) * 3 + c];
    float y = yc[(b * NC + t) * 3 + c];

    scnt[t] = 0;
    scnt[NC + t] = 0;

    float mn = x, mx = x;
#pragma unroll
    for (int off = 16; off > 0; off >>= 1) {
        mn = fminf(mn, __shfl_xor_sync(0xffffffffu, mn, off));
        mx = fmaxf(mx, __shfl_xor_sync(0xffffffffu, mx, off));
    }
    if (lane == 0) { wmn[w] = mn; wmx[w] = mx; }
    __syncthreads();
    if (t == 0) {
        float m = wmn[0], M = wmx[0];
#pragma unroll
        for (int i = 1; i < 16; i++) { m = fminf(m, wmn[i]); M = fmaxf(M, wmx[i]); }
        sminv = m;
        sscale = (M > m) ? 63.9999f / (M - m) : 0.0f;
    }
    __syncthreads();

    const float mnv = sminv, sc = sscale;
    int bin = (int)((x - mnv) * sc);
    bin = min(max(bin, 0), NBIN - 1);

    unsigned msk = __match_any_sync(0xffffffffu, bin);
    int rank = __popc(msk & ((1u << lane) - 1u));
    if (rank == 0) scnt[w * NBIN + bin] = __popc(msk);
    __syncthreads();

    if (t < NBIN) {
        int run = 0;
#pragma unroll
        for (int w2 = 0; w2 < 16; w2++) {
            int v = scnt[w2 * NBIN + t];
            scnt[w2 * NBIN + t] = run;
            run += v;
        }
        stotal[t] = run;
    }
    __syncthreads();

    for (int off = 1; off < NBIN; off <<= 1) {
        int v = 0;
        if (t < NBIN && t >= off) v = stotal[t - off];
        __syncthreads();
        if (t < NBIN && t >= off) stotal[t] += v;
        __syncthreads();
    }
    if (t < NBIN) sbstart[t + 1] = stotal[t];
    if (t == 0) sbstart[0] = 0;
    __syncthreads();

    int pos = sbstart[bin] + scnt[w * NBIN + bin] + rank;
    sx[pos] = x;
    sy[pos] = y;
    __syncthreads();

    g_sxy[bc * NC + t] = make_float2(sx[t], sy[t]);
    if (t < NBIN + 1) g_bstart[bc * (NBIN + 1) + t] = sbstart[t];
    if (t == 0) { g_binfo[bc * 2] = mnv; g_binfo[bc * 2 + 1] = sc; }
}

// ============================================================
// Kernel 1: windowed RBF sums + fourier prior (unchanged R12).
// ============================================================
__global__ void __launch_bounds__(256)
k1_rbf(const float* __restrict__ xg, const float* __restrict__ sigma,
       const float* __restrict__ mu, const float* __restrict__ eps1,
       const float* __restrict__ bu, const float* __restrict__ rw,
       float* __restrict__ out)
{
    __shared__ float2 sxy[3 * NC];
    __shared__ int sbs[3 * (NBIN + 1)];
    __shared__ float sminf[3], sscalef[3];
    __shared__ float ssw[NBAS * 3], ssb[NBAS * 3], srw[NBAS];
    __shared__ float scoef[3];
    __shared__ float sRmax;

    const int b = blockIdx.y;
    const int tid = threadIdx.x;

    for (int idx = tid; idx < 3 * NC; idx += 256)
        sxy[idx] = g_sxy[b * 3 * NC + idx];
    for (int idx = tid; idx < 3 * (NBIN + 1); idx += 256)
        sbs[idx] = g_bstart[b * 3 * (NBIN + 1) + idx];
    if (tid < 3) {
        sminf[tid]   = g_binfo[(b * 3 + tid) * 2];
        sscalef[tid] = g_binfo[(b * 3 + tid) * 2 + 1];
    }
    if (tid >= 128 && tid < 128 + NBAS * 3) {
        int q = tid - 128;
        int k = q / 3, p = q - k * 3;
        float w_std = 1.0f / (expf(sigma[p]) + EPSV);
        ssw[q] = expf(mu[p]) + w_std * eps1[(b * NBAS + k) * 3 + p];
        ssb[q] = 6.283185307179586f * bu[(b * NBAS + k) * 3 + p];
    }
    if (tid >= 160 && tid < 160 + NBAS) srw[tid - 160] = rw[tid - 160];
    if (tid >= 176 && tid < 179) {
        int p = tid - 176;
        float s = expf(sigma[p]) + EPSV;
        float inv = 1.0f / s;
        scoef[p] = -0.5f * inv * inv * 1.4426950408889634f;
    }
    if (tid == 192) {
        float s0 = expf(sigma[0]) + EPSV;
        float s1 = expf(sigma[1]) + EPSV;
        float s2 = expf(sigma[2]) + EPSV;
        sRmax = 8.5f * fmaxf(s0, fmaxf(s1, s2));
    }
    __syncthreads();

    const int wid = tid >> 5, lane = tid & 31;
    const int g = blockIdx.x * 8 + wid;
    const float* xgp = &xg[(b * NG + g) * 3];
    const float xgv[3] = { xgp[0], xgp[1], xgp[2] };
    const float c0 = scoef[0], c1 = scoef[1], c2 = scoef[2];
    const float R = sRmax;

    float h0[9], h1[9];

#pragma unroll
    for (int c = 0; c < 3; c++) {
        const float xgc = xgv[c];
        const float2* sp = sxy + c * NC;
        const int* bsc = sbs + c * (NBIN + 1);
        const float mnc = sminf[c], scc = sscalef[c];

        int il = (int)floorf((xgc - R - mnc) * scc);
        int ih = (int)floorf((xgc + R - mnc) * scc);
        il = min(max(il, 0), NBIN - 1);
        ih = min(max(ih, 0), NBIN - 1);
        const int lo = bsc[il], hi = bsc[ih + 1];

        float a0 = 0.f, a1 = 0.f, a2 = 0.f;
        float b0 = 0.f, b1 = 0.f, b2 = 0.f;
        for (int n = lo + lane; n < hi; n += 32) {
            float2 v = sp[n];
            float d = v.x - xgc;
            float s = d * d;
            float e;
            e = ex2f(s * c0); a0 += e; b0 = fmaf(e, v.y, b0);
            e = ex2f(s * c1); a1 += e; b1 = fmaf(e, v.y, b1);
            e = ex2f(s * c2); a2 += e; b2 = fmaf(e, v.y, b2);
        }
        h0[c * 3 + 0] = a0; h1[c * 3 + 0] = b0;
        h0[c * 3 + 1] = a1; h1[c * 3 + 1] = b1;
        h0[c * 3 + 2] = a2; h1[c * 3 + 2] = b2;
    }

#pragma unroll
    for (int off = 16; off > 0; off >>= 1) {
#pragma unroll
        for (int j = 0; j < 9; j++) {
            h0[j] += __shfl_xor_sync(0xffffffffu, h0[j], off);
            h1[j] += __shfl_xor_sync(0xffffffffu, h1[j], off);
        }
    }

    if (lane < 9) {
        float h0v = 0.f, h1v = 0.f;
        switch (lane) {
            case 0: h0v = h0[0]; h1v = h1[0]; break;
            case 1: h0v = h0[1]; h1v = h1[1]; break;
            case 2: h0v = h0[2]; h1v = h1[2]; break;
            case 3: h0v = h0[3]; h1v = h1[3]; break;
            case 4: h0v = h0[4]; h1v = h1[4]; break;
            case 5: h0v = h0[5]; h1v = h1[5]; break;
            case 6: h0v = h0[6]; h1v = h1[6]; break;
            case 7: h0v = h0[7]; h1v = h1[7]; break;
            case 8: h0v = h0[8]; h1v = h1[8]; break;
        }
        int c = lane / 3;
        int p = lane - c * 3;
        float xgc = xgv[c];
        float nh1 = h1v / (h0v + EPSV);

        // mul-then-add (no FMA) to match reference fp32 arg exactly
        float fp = 0.f;
#pragma unroll
        for (int k = 0; k < NBAS; k++) {
            float arg = __fadd_rn(__fmul_rn(ssw[k * 3 + p], xgc), ssb[k * 3 + p]);
            fp += srw[k] * cosf(arg);
        }
        fp *= 0.4472135954999579f;

        int pt = b * NG + g;
        int base = pt * 9 + lane;
        out[OFF_H0 + base] = h0v;
        out[OFF_NH1 + base] = nh1;
        out[OFF_FP + base] = fp;
        g_pos[lane * NPT + pt] = nh1 + fp;
    }
}

// ============================================================
// Kernel 2: depthwise convs + deterministic BN partial sums
//           (unchanged R12).
// ============================================================
__global__ void __launch_bounds__(512)
k2_conv(const float* __restrict__ w1, const float* __restrict__ b1,
        const float* __restrict__ w2, const float* __restrict__ b2,
        const float* __restrict__ w3, const float* __restrict__ b3)
{
    __shared__ double ss[512], sq[512];
    const int tid = threadIdx.x;
    const int t = blockIdx.x * 512 + tid;
    const int chan = blockIdx.x >> 4;
    const int rem = t - chan * NPT;
    const int g = rem & (NG - 1);
    const int c = chan / 3, p = chan - c * 3;

    const int ksz = (p == 0) ? 3 : ((p == 1) ? 5 : 9);
    const int pad = ksz >> 1;
    const float* w  = (p == 0) ? w1 : ((p == 1) ? w2 : w3);
    const float* bb = (p == 0) ? b1 : ((p == 1) ? b2 : b3);

    float acc = bb[c];
    const float* src = &g_pos[t - g];
    for (int tt = 0; tt < ksz; tt++) {
        int gg = g + tt - pad;
        if (gg >= 0 && gg < NG)
            acc = fmaf(src[gg], w[c * ksz + tt], acc);
    }
    g_conv[t] = acc;

    double v = (double)acc;
    ss[tid] = v;
    sq[tid] = v * v;
    __syncthreads();
    for (int off = 256; off > 0; off >>= 1) {
        if (tid < off) { ss[tid] += ss[tid + off]; sq[tid] += sq[tid + off]; }
        __syncthreads();
    }
    if (tid == 0) {
        long long is = __double2ll_rn(ss[0] * S_SUM);
        long long iq = __double2ll_rn(sq[0] * S_SQ);
        atomicAdd(&g_isum[chan], (unsigned long long)is);
        atomicAdd(&g_isq[chan],  (unsigned long long)iq);
    }
}

// ============================================================
// Kernel 3 (REWRITTEN): warp-per-point, barrier-free mainloop.
//           Lane k<18 holds feature k in a register; 18-step
//           shfl-broadcast matvec against smem weights; coalesced
//           Y stores. One staging barrier per block total.
// ============================================================
__global__ void __launch_bounds__(256)
k3_head(const float* __restrict__ gamma, const float* __restrict__ beta,
        const float* __restrict__ gw, const float* __restrict__ gb,
        float* __restrict__ out)
{
    __shared__ float swT[18 * 64];       // [k][o]
    __shared__ float sbias[OC];
    __shared__ float sstat[18];
    __shared__ float sgam[9], sbet[9];

    const int tid = threadIdx.x;

    // stage weights (transposed), bias, stats, BN params -- once
    for (int idx = tid; idx < OC * 18; idx += 256) {
        int o = idx / 18, k = idx - o * 18;
        swT[k * 64 + o] = gw[idx];
    }
    if (tid < OC) sbias[tid] = gb[tid];
    if (tid >= 96 && tid < 105) {
        int j = tid - 96;
        int c = j / 3, p = j - c * 3;
        sgam[j] = gamma[p * 3 + c];
        sbet[j] = beta[p * 3 + c];
    }
    if (tid >= 64 && tid < 73) {
        int j = tid - 64;
        double m  = (double)(long long)g_isum[j] * (1.0 / S_SUM) * (1.0 / 8192.0);
        double eq = (double)(long long)g_isq[j]  * (1.0 / S_SQ)  * (1.0 / 8192.0);
        double var = eq - m * m;
        if (var < 0.0) var = 0.0;
        sstat[j] = (float)m;
        sstat[9 + j] = (float)(1.0 / sqrt(var + (double)BN_EPS));
    }
    __syncthreads();

    const int wid = tid >> 5, lane = tid & 31;
    const int gwarp = blockIdx.x * 8 + wid;
    const int nwarp = gridDim.x * 8;
    const float bias0 = sbias[lane], bias1 = sbias[lane + 32];

    for (int pt = gwarp; pt < NPT; pt += nwarp) {
        // lane k in [0,9): h0 feat k ; lane k in [9,18): BN(conv) feat k
        float f = 0.f;
        if (lane < 9) {
            f = out[OFF_H0 + pt * 9 + lane];
        } else if (lane < 18) {
            int j = lane - 9;
            float x = g_conv[j * NPT + pt];
            f = sgam[j] * (x - sstat[j]) * sstat[9 + j] + sbet[j];
            out[OFF_NF + pt * 9 + j] = f;     // n_f
        }

        float acc0 = bias0, acc1 = bias1;
#pragma unroll
        for (int k = 0; k < 18; k++) {
            float fv = __shfl_sync(0xffffffffu, f, k);
            acc0 = fmaf(fv, swT[k * 64 + lane], acc0);
            acc1 = fmaf(fv, swT[k * 64 + lane + 32], acc1);
        }
        out[OFF_Y + pt * OC + lane] = acc0;
        out[OFF_Y + pt * OC + lane + 32] = acc1;
    }
}

// ============================================================
extern "C" void kernel_launch(void* const* d_in, const int* in_sizes, int n_in,
                              void* d_out, int out_size)
{
    const float* xc    = (const float*)d_in[0];
    const float* yc    = (const float*)d_in[1];
    const float* xg    = (const float*)d_in[2];
    const float* sigma = (const float*)d_in[3];
    const float* mu    = (const float*)d_in[4];
    const float* eps1  = (const float*)d_in[5];
    const float* bu    = (const float*)d_in[6];
    const float* rw    = (const float*)d_in[7];
    const float* w1    = (const float*)d_in[8];
    const float* b1    = (const float*)d_in[9];
    const float* w2    = (const float*)d_in[10];
    const float* b2    = (const float*)d_in[11];
    const float* w3    = (const float*)d_in[12];
    const float* b3    = (const float*)d_in[13];
    const float* gamma = (const float*)d_in[14];
    const float* beta  = (const float*)d_in[15];
    const float* gw    = (const float*)d_in[16];
    const float* gb    = (const float*)d_in[17];
    float* out = (float*)d_out;

    k0_bucket<<<NB * 3, NC>>>(xc, yc);
    dim3 grid1(NG / 8, NB);
    k1_rbf<<<grid1, 256>>>(xg, sigma, mu, eps1, bu, rw, out);
    k2_conv<<<144, 512>>>(w1, b1, w2, b2, w3, b3);
    k3_head<<<296, 256>>>(gamma, beta, gw, gb, out);
}

// round 14
// speedup vs baseline: 1.4185x; 1.0804x over previous
#include <cuda_runtime.h>
#include <cstdint>

// ---------------- problem constants ----------------
#define NB 4
#define NC 512
#define NG 2048
#define CH 3
#define OC 64
#define NBAS 10
#define NPT 8192
#define NBIN 64
#define EPSV 1e-6f
#define BN_EPS 1e-5f

// output layout (float32, concatenated in return order)
#define OFF_Y   0
#define OFF_NF  524288
#define OFF_FP  598016
#define OFF_NH1 671744
#define OFF_H0  745472

// scratch (device globals)
__device__ float g_pos[9 * NPT];          // SoA [chan][b*NG+g]
__device__ float g_conv[9 * NPT];
__device__ float2 g_sxy[NB * 3 * NC];     // bucketed (x,y) per (b,coord)
__device__ int   g_bstart[NB * 3 * (NBIN + 1)];
__device__ float g_binfo[NB * 3 * 2];     // min, scale per (b,coord)
__device__ unsigned long long g_isum[9];
__device__ unsigned long long g_isq[9];

#define S_SUM 1.7179869184e10   // 2^34
#define S_SQ  2.68435456e8      // 2^28

__device__ __forceinline__ float ex2f(float x) {
    float y;
    asm("ex2.approx.ftz.f32 %0, %1;" : "=f"(y) : "f"(x));
    return y;
}

// ============================================================
// Kernel 0: deterministic 64-bin bucket multisplit per (b,coord).
//           (unchanged -- proven R10/R12)
// ============================================================
__global__ void __launch_bounds__(NC)
k0_bucket(const float* __restrict__ xc, const float* __restrict__ yc)
{
    __shared__ float sx[NC], sy[NC];
    __shared__ int scnt[16 * NBIN];      // [warp][bin]
    __shared__ int stotal[NBIN];
    __shared__ int sbstart[NBIN + 1];
    __shared__ float wmn[16], wmx[16];
    __shared__ float sminv, sscale;

    const int bc = blockIdx.x;           // 0..11
    const int b = bc / 3, c = bc - b * 3;
    const int t = threadIdx.x;
    const int w = t >> 5, lane = t & 31;

    if (bc == 0 && t < 9) { g_isum[t] = 0ull; g_isq[t] = 0ull; }

    float x = xc[(b * NC + t) * 3 + c];
    float y = yc[(b * NC + t) * 3 + c];

    scnt[t] = 0;
    scnt[NC + t] = 0;

    float mn = x, mx = x;
#pragma unroll
    for (int off = 16; off > 0; off >>= 1) {
        mn = fminf(mn, __shfl_xor_sync(0xffffffffu, mn, off));
        mx = fmaxf(mx, __shfl_xor_sync(0xffffffffu, mx, off));
    }
    if (lane == 0) { wmn[w] = mn; wmx[w] = mx; }
    __syncthreads();
    if (t == 0) {
        float m = wmn[0], M = wmx[0];
#pragma unroll
        for (int i = 1; i < 16; i++) { m = fminf(m, wmn[i]); M = fmaxf(M, wmx[i]); }
        sminv = m;
        sscale = (M > m) ? 63.9999f / (M - m) : 0.0f;
    }
    __syncthreads();

    const float mnv = sminv, sc = sscale;
    int bin = (int)((x - mnv) * sc);
    bin = min(max(bin, 0), NBIN - 1);

    unsigned msk = __match_any_sync(0xffffffffu, bin);
    int rank = __popc(msk & ((1u << lane) - 1u));
    if (rank == 0) scnt[w * NBIN + bin] = __popc(msk);
    __syncthreads();

    if (t < NBIN) {
        int run = 0;
#pragma unroll
        for (int w2 = 0; w2 < 16; w2++) {
            int v = scnt[w2 * NBIN + t];
            scnt[w2 * NBIN + t] = run;
            run += v;
        }
        stotal[t] = run;
    }
    __syncthreads();

    for (int off = 1; off < NBIN; off <<= 1) {
        int v = 0;
        if (t < NBIN && t >= off) v = stotal[t - off];
        __syncthreads();
        if (t < NBIN && t >= off) stotal[t] += v;
        __syncthreads();
    }
    if (t < NBIN) sbstart[t + 1] = stotal[t];
    if (t == 0) sbstart[0] = 0;
    __syncthreads();

    int pos = sbstart[bin] + scnt[w * NBIN + bin] + rank;
    sx[pos] = x;
    sy[pos] = y;
    __syncthreads();

    g_sxy[bc * NC + t] = make_float2(sx[t], sy[t]);
    if (t < NBIN + 1) g_bstart[bc * (NBIN + 1) + t] = sbstart[t];
    if (t == 0) { g_binfo[bc * 2] = mnv; g_binfo[bc * 2 + 1] = sc; }
}

// ============================================================
// Kernel 1: windowed RBF sums + fourier prior.
//           NEW epilogue: 2-step butterfly + smem gather reduce,
//           and 27-lane parallel fourier (4 uniform cos/lane).
// ============================================================
__global__ void __launch_bounds__(256)
k1_rbf(const float* __restrict__ xg, const float* __restrict__ sigma,
       const float* __restrict__ mu, const float* __restrict__ eps1,
       const float* __restrict__ bu, const float* __restrict__ rw,
       float* __restrict__ out)
{
    __shared__ float2 sxy[3 * NC];
    __shared__ int sbs[3 * (NBIN + 1)];
    __shared__ float sminf[3], sscalef[3];
    __shared__ float ssw[NBAS * 3], ssb[NBAS * 3];
    __shared__ float scoef[3];
    __shared__ float sRmax;
    __shared__ int   sktab[12];          // fourier k-index table [grp*4+i]
    __shared__ float swgt[12];           // fourier weights (0 = dummy pad)
    __shared__ float sred[8][144];       // per-warp reduce scratch [r<8][18]

    const int b = blockIdx.y;
    const int tid = threadIdx.x;

    for (int idx = tid; idx < 3 * NC; idx += 256)
        sxy[idx] = g_sxy[b * 3 * NC + idx];
    for (int idx = tid; idx < 3 * (NBIN + 1); idx += 256)
        sbs[idx] = g_bstart[b * 3 * (NBIN + 1) + idx];
    if (tid < 3) {
        sminf[tid]   = g_binfo[(b * 3 + tid) * 2];
        sscalef[tid] = g_binfo[(b * 3 + tid) * 2 + 1];
    }
    if (tid >= 128 && tid < 128 + NBAS * 3) {
        int q = tid - 128;
        int k = q / 3, p = q - k * 3;
        float w_std = 1.0f / (expf(sigma[p]) + EPSV);
        ssw[q] = expf(mu[p]) + w_std * eps1[(b * NBAS + k) * 3 + p];
        ssb[q] = 6.283185307179586f * bu[(b * NBAS + k) * 3 + p];
    }
    if (tid >= 176 && tid < 179) {
        int p = tid - 176;
        float s = expf(sigma[p]) + EPSV;
        float inv = 1.0f / s;
        scoef[p] = -0.5f * inv * inv * 1.4426950408889634f;
    }
    if (tid == 192) {
        float s0 = expf(sigma[0]) + EPSV;
        float s1 = expf(sigma[1]) + EPSV;
        float s2 = expf(sigma[2]) + EPSV;
        sRmax = 8.5f * fmaxf(s0, fmaxf(s1, s2));
    }
    // fourier k table: grp0 -> k{0,1,2,3}, grp1 -> k{4,5,6,pad}, grp2 -> k{7,8,9,pad}
    if (tid >= 200 && tid < 212) {
        int e = tid - 200;
        int grp = e >> 2, i = e & 3;
        int kk; float wv;
        if (grp == 0)      { kk = i;                       wv = rw[i]; }
        else if (grp == 1) { kk = (i < 3) ? 4 + i : 0;     wv = (i < 3) ? rw[4 + i] : 0.f; }
        else               { kk = (i < 3) ? 7 + i : 0;     wv = (i < 3) ? rw[7 + i] : 0.f; }
        sktab[e] = kk;
        swgt[e] = wv;
    }
    __syncthreads();

    const int wid = tid >> 5, lane = tid & 31;
    const int g = blockIdx.x * 8 + wid;
    const float* xgp = &xg[(b * NG + g) * 3];
    const float xg0 = xgp[0], xg1 = xgp[1], xg2 = xgp[2];
    const float c0 = scoef[0], c1 = scoef[1], c2 = scoef[2];
    const float R = sRmax;

    float h0[9], h1[9];

    {
        const float xgv3[3] = { xg0, xg1, xg2 };
#pragma unroll
        for (int c = 0; c < 3; c++) {
            const float xgc = xgv3[c];
            const float2* sp = sxy + c * NC;
            const int* bsc = sbs + c * (NBIN + 1);
            const float mnc = sminf[c], scc = sscalef[c];

            int il = (int)floorf((xgc - R - mnc) * scc);
            int ih = (int)floorf((xgc + R - mnc) * scc);
            il = min(max(il, 0), NBIN - 1);
            ih = min(max(ih, 0), NBIN - 1);
            const int lo = bsc[il], hi = bsc[ih + 1];

            float a0 = 0.f, a1 = 0.f, a2 = 0.f;
            float b0 = 0.f, b1 = 0.f, b2 = 0.f;
            for (int n = lo + lane; n < hi; n += 32) {
                float2 v = sp[n];
                float d = v.x - xgc;
                float s = d * d;
                float e;
                e = ex2f(s * c0); a0 += e; b0 = fmaf(e, v.y, b0);
                e = ex2f(s * c1); a1 += e; b1 = fmaf(e, v.y, b1);
                e = ex2f(s * c2); a2 += e; b2 = fmaf(e, v.y, b2);
            }
            h0[c * 3 + 0] = a0; h1[c * 3 + 0] = b0;
            h0[c * 3 + 1] = a1; h1[c * 3 + 1] = b1;
            h0[c * 3 + 2] = a2; h1[c * 3 + 2] = b2;
        }
    }

    // partial butterfly: offsets 16, 8 -> lane holds sum over lanes == lane (mod 8)
#pragma unroll
    for (int off = 16; off >= 8; off >>= 1) {
#pragma unroll
        for (int j = 0; j < 9; j++) {
            h0[j] += __shfl_xor_sync(0xffffffffu, h0[j], off);
            h1[j] += __shfl_xor_sync(0xffffffffu, h1[j], off);
        }
    }
    // smem gather: lanes 0..7 store 18 partials; lanes 0..17 sum 8 each
    if (lane < 8) {
#pragma unroll
        for (int j = 0; j < 9; j++) {
            sred[wid][lane * 18 + j]     = h0[j];
            sred[wid][lane * 18 + 9 + j] = h1[j];
        }
    }
    __syncwarp();
    float hsum = 0.f;
    {
        int le = (lane < 18) ? lane : 0;
#pragma unroll
        for (int r = 0; r < 8; r++)
            hsum += sred[wid][r * 18 + le];
    }
    // hsum: lane<9 = h0[chan=lane], lane in [9,18) = h1[chan=lane-9]
    float h1v = __shfl_sync(0xffffffffu, hsum, lane + 9);   // valid for lane<9

    // fourier: 27 lanes, 4 uniform cos each (zero-weight pads), no divergence
    float fpart = 0.f;
    {
        int le = (lane < 27) ? lane : 26;
        int grp = le / 9;
        int j = le - grp * 9;
        int c = j / 3, p = j - c * 3;
        float xgc = (c == 0) ? xg0 : ((c == 1) ? xg1 : xg2);
#pragma unroll
        for (int i = 0; i < 4; i++) {
            int e = grp * 4 + i;
            int kk = sktab[e];
            float arg = __fadd_rn(__fmul_rn(ssw[kk * 3 + p], xgc), ssb[kk * 3 + p]);
            fpart = fmaf(swgt[e], cosf(arg), fpart);
        }
    }
    float fpB = __shfl_sync(0xffffffffu, fpart, lane + 9);   // valid for lane<9
    float fpC = __shfl_sync(0xffffffffu, fpart, lane + 18);

    if (lane < 9) {
        float h0v = hsum;
        float nh1 = h1v / (h0v + EPSV);
        float fp = ((fpart + fpB) + fpC) * 0.4472135954999579f;   // sqrt(2/10)

        int pt = b * NG + g;
        int base = pt * 9 + lane;
        out[OFF_H0 + base] = h0v;
        out[OFF_NH1 + base] = nh1;
        out[OFF_FP + base] = fp;
        g_pos[lane * NPT + pt] = nh1 + fp;
    }
}

// ============================================================
// Kernel 2: depthwise convs + deterministic BN partial sums
//           (unchanged R12).
// ============================================================
__global__ void __launch_bounds__(512)
k2_conv(const float* __restrict__ w1, const float* __restrict__ b1,
        const float* __restrict__ w2, const float* __restrict__ b2,
        const float* __restrict__ w3, const float* __restrict__ b3)
{
    __shared__ double ss[512], sq[512];
    const int tid = threadIdx.x;
    const int t = blockIdx.x * 512 + tid;
    const int chan = blockIdx.x >> 4;
    const int rem = t - chan * NPT;
    const int g = rem & (NG - 1);
    const int c = chan / 3, p = chan - c * 3;

    const int ksz = (p == 0) ? 3 : ((p == 1) ? 5 : 9);
    const int pad = ksz >> 1;
    const float* w  = (p == 0) ? w1 : ((p == 1) ? w2 : w3);
    const float* bb = (p == 0) ? b1 : ((p == 1) ? b2 : b3);

    float acc = bb[c];
    const float* src = &g_pos[t - g];
    for (int tt = 0; tt < ksz; tt++) {
        int gg = g + tt - pad;
        if (gg >= 0 && gg < NG)
            acc = fmaf(src[gg], w[c * ksz + tt], acc);
    }
    g_conv[t] = acc;

    double v = (double)acc;
    ss[tid] = v;
    sq[tid] = v * v;
    __syncthreads();
    for (int off = 256; off > 0; off >>= 1) {
        if (tid < off) { ss[tid] += ss[tid + off]; sq[tid] += sq[tid + off]; }
        __syncthreads();
    }
    if (tid == 0) {
        long long is = __double2ll_rn(ss[0] * S_SUM);
        long long iq = __double2ll_rn(sq[0] * S_SQ);
        atomicAdd(&g_isum[chan], (unsigned long long)is);
        atomicAdd(&g_isq[chan],  (unsigned long long)iq);
    }
}

// ============================================================
// Kernel 3: warp-per-point barrier-free head (unchanged R13).
// ============================================================
__global__ void __launch_bounds__(256)
k3_head(const float* __restrict__ gamma, const float* __restrict__ beta,
        const float* __restrict__ gw, const float* __restrict__ gb,
        float* __restrict__ out)
{
    __shared__ float swT[18 * 64];       // [k][o]
    __shared__ float sbias[OC];
    __shared__ float sstat[18];
    __shared__ float sgam[9], sbet[9];

    const int tid = threadIdx.x;

    for (int idx = tid; idx < OC * 18; idx += 256) {
        int o = idx / 18, k = idx - o * 18;
        swT[k * 64 + o] = gw[idx];
    }
    if (tid < OC) sbias[tid] = gb[tid];
    if (tid >= 96 && tid < 105) {
        int j = tid - 96;
        int c = j / 3, p = j - c * 3;
        sgam[j] = gamma[p * 3 + c];
        sbet[j] = beta[p * 3 + c];
    }
    if (tid >= 64 && tid < 73) {
        int j = tid - 64;
        double m  = (double)(long long)g_isum[j] * (1.0 / S_SUM) * (1.0 / 8192.0);
        double eq = (double)(long long)g_isq[j]  * (1.0 / S_SQ)  * (1.0 / 8192.0);
        double var = eq - m * m;
        if (var < 0.0) var = 0.0;
        sstat[j] = (float)m;
        sstat[9 + j] = (float)(1.0 / sqrt(var + (double)BN_EPS));
    }
    __syncthreads();

    const int wid = tid >> 5, lane = tid & 31;
    const int gwarp = blockIdx.x * 8 + wid;
    const int nwarp = gridDim.x * 8;
    const float bias0 = sbias[lane], bias1 = sbias[lane + 32];

    for (int pt = gwarp; pt < NPT; pt += nwarp) {
        float f = 0.f;
        if (lane < 9) {
            f = out[OFF_H0 + pt * 9 + lane];
        } else if (lane < 18) {
            int j = lane - 9;
            float x = g_conv[j * NPT + pt];
            f = sgam[j] * (x - sstat[j]) * sstat[9 + j] + sbet[j];
            out[OFF_NF + pt * 9 + j] = f;
        }

        float acc0 = bias0, acc1 = bias1;
#pragma unroll
        for (int k = 0; k < 18; k++) {
            float fv = __shfl_sync(0xffffffffu, f, k);
            acc0 = fmaf(fv, swT[k * 64 + lane], acc0);
            acc1 = fmaf(fv, swT[k * 64 + lane + 32], acc1);
        }
        out[OFF_Y + pt * OC + lane] = acc0;
        out[OFF_Y + pt * OC + lane + 32] = acc1;
    }
}

// ============================================================
extern "C" void kernel_launch(void* const* d_in, const int* in_sizes, int n_in,
                              void* d_out, int out_size)
{
    const float* xc    = (const float*)d_in[0];
    const float* yc    = (const float*)d_in[1];
    const float* xg    = (const float*)d_in[2];
    const float* sigma = (const float*)d_in[3];
    const float* mu    = (const float*)d_in[4];
    const float* eps1  = (const float*)d_in[5];
    const float* bu    = (const float*)d_in[6];
    const float* rw    = (const float*)d_in[7];
    const float* w1    = (const float*)d_in[8];
    const float* b1    = (const float*)d_in[9];
    const float* w2    = (const float*)d_in[10];
    const float* b2    = (const float*)d_in[11];
    const float* w3    = (const float*)d_in[12];
    const float* b3    = (const float*)d_in[13];
    const float* gamma = (const float*)d_in[14];
    const float* beta  = (const float*)d_in[15];
    const float* gw    = (const float*)d_in[16];
    const float* gb    = (const float*)d_in[17];
    float* out = (float*)d_out;

    k0_bucket<<<NB * 3, NC>>>(xc, yc);
    dim3 grid1(NG / 8, NB);
    k1_rbf<<<grid1, 256>>>(xg, sigma, mu, eps1, bu, rw, out);
    k2_conv<<<144, 512>>>(w1, b1, w2, b2, w3, b3);
    k3_head<<<296, 256>>>(gamma, beta, gw, gb, out);
}